// round 15
// baseline (speedup 1.0000x reference)
#include <cuda_runtime.h>
#include <cuda_bf16.h>
#include <cstdint>
#include <cstddef>

#define NN_MAX 100000
#define NE_MAX 1600000
#define CH 128

// Scratch (static __device__ allocation is the sanctioned workaround)
__device__ float g_x0[(size_t)NN_MAX * CH];
__device__ float g_x1[(size_t)NN_MAX * CH];
__device__ float g_agg[(size_t)NN_MAX * CH];
__device__ int2  g_epk[(size_t)NE_MAX];
__device__ int   g_is64;
// CSR structures (dst is layer-invariant; built once per launch)
__device__ int   g_cnt[NN_MAX];
__device__ int   g_off[NN_MAX + 1];
__device__ int   g_part[512];
__device__ int   g_perm[NE_MAX];
__device__ int   g_srcs[NE_MAX];
__device__ int   g_pnode[NE_MAX];
// Pre-packed B fragments for mma.m16n8k16:
__device__ uint2 g_Bfrag[4 * 2 * 16 * 2 * 32];          // We  [layer][part][nt16][ks2][lane]
__device__ uint2 g_W1frag[4 * 2 * 8 * 32 * 32];         // W1  [layer][part][ks8][nt32][lane]
__device__ uint2 g_W2frag[4 * 2 * 16 * 16 * 32];        // W2  [layer][part][ks16][nt16][lane]

// ---------- f32x2 helpers ----------
__device__ __forceinline__ unsigned long long pack2(float a, float b) {
    unsigned long long r;
    asm("mov.b64 %0, {%1, %2};" : "=l"(r) : "f"(a), "f"(b));
    return r;
}
__device__ __forceinline__ float2 unpack2(unsigned long long v) {
    float2 f;
    asm("mov.b64 {%0, %1}, %2;" : "=f"(f.x), "=f"(f.y) : "l"(v));
    return f;
}
__device__ __forceinline__ unsigned long long fma2(unsigned long long a,
                                                   unsigned long long b,
                                                   unsigned long long c) {
    unsigned long long d;
    asm("fma.rn.f32x2 %0, %1, %2, %3;" : "=l"(d) : "l"(a), "l"(b), "l"(c));
    return d;
}
__device__ __forceinline__ void red4(float* p, float a, float b, float c, float d) {
    asm volatile("red.global.add.v4.f32 [%0], {%1, %2, %3, %4};"
                 :: "l"(p), "f"(a), "f"(b), "f"(c), "f"(d) : "memory");
}

// ---------- mma.sync helpers (baseline PTX; works on plain sm_103 target) ----------
__device__ __forceinline__ uint32_t smem_u32(const void* p) {
    uint32_t a;
    asm("{ .reg .u64 t; cvta.to.shared.u64 t, %1; cvt.u32.u64 %0, t; }" : "=r"(a) : "l"(p));
    return a;
}
__device__ __forceinline__ void ldmatrix_x4(uint32_t& r0, uint32_t& r1,
                                            uint32_t& r2, uint32_t& r3, uint32_t addr) {
    asm volatile("ldmatrix.sync.aligned.m8n8.x4.shared.b16 {%0,%1,%2,%3}, [%4];"
                 : "=r"(r0), "=r"(r1), "=r"(r2), "=r"(r3) : "r"(addr));
}
__device__ __forceinline__ void mma_bf16(float* c, const uint32_t* a, uint2 b) {
    asm volatile("mma.sync.aligned.m16n8k16.row.col.f32.bf16.bf16.f32 "
                 "{%0,%1,%2,%3}, {%4,%5,%6,%7}, {%8,%9}, {%0,%1,%2,%3};"
                 : "+f"(c[0]), "+f"(c[1]), "+f"(c[2]), "+f"(c[3])
                 : "r"(a[0]), "r"(a[1]), "r"(a[2]), "r"(a[3]), "r"(b.x), "r"(b.y));
}
__device__ __forceinline__ uint32_t pack_bf16(__nv_bfloat16 lo, __nv_bfloat16 hi) {
    uint16_t l = *(uint16_t*)&lo, h = *(uint16_t*)&hi;
    return (uint32_t)l | ((uint32_t)h << 16);
}
__device__ __forceinline__ uint32_t hilo_hi(float a, float b) {
    return pack_bf16(__float2bfloat16(a), __float2bfloat16(b));
}
__device__ __forceinline__ uint32_t hilo_lo(float a, float b) {
    __nv_bfloat16 ha = __float2bfloat16(a), hb = __float2bfloat16(b);
    return pack_bf16(__float2bfloat16(a - __bfloat162float(ha)),
                     __float2bfloat16(b - __bfloat162float(hb)));
}

// ---------- dtype detection + index canonicalization ----------
__global__ void detect_kernel(const unsigned int* e32) {
    if (threadIdx.x == 0 && blockIdx.x == 0) {
        int is64 = 1;
        for (int i = 0; i < 256; i += 2)
            if (e32[i + 1] != 0u) is64 = 0;
        g_is64 = is64;
    }
}

__global__ void convert_kernel(const void* ei, int nE) {
    int f = g_is64;
    int i = blockIdx.x * blockDim.x + threadIdx.x;
    int stride = gridDim.x * blockDim.x;
    if (f) {
        const long long* p = (const long long*)ei;
        for (; i < nE; i += stride)
            g_epk[i] = make_int2((int)p[i], (int)p[nE + i]);
    } else {
        const int* p = (const int*)ei;
        for (; i < nE; i += stride)
            g_epk[i] = make_int2(p[i], p[nE + i]);
    }
}

// ---------- CSR build ----------
__global__ void hist_kernel(int nE) {
    int i = blockIdx.x * blockDim.x + threadIdx.x;
    if (i < nE) atomicAdd(&g_cnt[g_epk[i].y], 1);
}

__global__ void scanA_kernel(int n) {
    __shared__ int sd[256];
    int tid = threadIdx.x;
    int i = blockIdx.x * 256 + tid;
    int v = (i < n) ? g_cnt[i] : 0;
    sd[tid] = v;
    __syncthreads();
    for (int d = 1; d < 256; d <<= 1) {
        int u = (tid >= d) ? sd[tid - d] : 0;
        __syncthreads();
        sd[tid] += u;
        __syncthreads();
    }
    if (i < n) g_off[i] = sd[tid] - v;
    if (tid == 255) g_part[blockIdx.x] = sd[255];
}
__global__ void __launch_bounds__(512) scanB_kernel(int nb) {
    __shared__ int sd[512];
    int tid = threadIdx.x;
    int v = (tid < nb) ? g_part[tid] : 0;
    sd[tid] = v;
    __syncthreads();
    for (int d = 1; d < 512; d <<= 1) {
        int u = (tid >= d) ? sd[tid - d] : 0;
        __syncthreads();
        sd[tid] += u;
        __syncthreads();
    }
    if (tid < nb) g_part[tid] = sd[tid] - v;
}
__global__ void scanC_kernel(int n) {
    int i = blockIdx.x * 256 + threadIdx.x;
    if (i < n) {
        int o = g_off[i] + g_part[blockIdx.x];
        g_off[i] = o;
        if (i == n - 1) g_off[n] = o + g_cnt[i];
    }
}

__global__ void scatter_kernel(int nE) {
    int e = blockIdx.x * blockDim.x + threadIdx.x;
    if (e < nE) {
        int d = g_epk[e].y;
        int pos = g_off[d] + atomicAdd(&g_cnt[d], 1);
        g_perm[pos] = e;
    }
}

__global__ void sortrow_kernel(int nNodes) {
    int n = blockIdx.x * blockDim.x + threadIdx.x;
    if (n >= nNodes) return;
    int s = g_off[n], e = g_off[n + 1];
    int deg = e - s;
    if (deg <= 1) return;
    if (deg <= 64) {
        int a[64];
        for (int i = 0; i < deg; i++) a[i] = g_perm[s + i];
        for (int i = 1; i < deg; i++) {
            int v = a[i], j = i - 1;
            while (j >= 0 && a[j] > v) { a[j + 1] = a[j]; j--; }
            a[j + 1] = v;
        }
        for (int i = 0; i < deg; i++) g_perm[s + i] = a[i];
    } else {
        for (int i = s + 1; i < e; i++) {
            int v = g_perm[i], j = i - 1;
            while (j >= s && g_perm[j] > v) { g_perm[j + 1] = g_perm[j]; j--; }
            g_perm[j + 1] = v;
        }
    }
}

__global__ void srcs_kernel(int nE) {
    int p = blockIdx.x * blockDim.x + threadIdx.x;
    if (p < nE) g_srcs[p] = g_epk[g_perm[p]].x;
}

// pos -> node id (binary search over g_off); built once
__global__ void pnode_kernel(int nE, int nNodes) {
    int pos = blockIdx.x * blockDim.x + threadIdx.x;
    if (pos >= nE) return;
    int lo = 0, hi = nNodes;
    while (hi - lo > 1) {
        int mid = (lo + hi) >> 1;
        if (g_off[mid] <= pos) lo = mid; else hi = mid;
    }
    g_pnode[pos] = lo;
}

// ---------- B-fragment prep ----------
__global__ void bprep_kernel(const float* __restrict__ We) {
    int i = blockIdx.x * blockDim.x + threadIdx.x;
    if (i >= 4 * 2 * 16 * 2 * 32) return;
    int lane = i & 31;
    int ks   = (i >> 5) & 1;
    int nt   = (i >> 6) & 15;
    int part = (i >> 10) & 1;
    int l    = i >> 11;
    int t = lane & 3, g = lane >> 2;
    int n = nt * 8 + g;
    int k0 = ks * 16 + 2 * t;
    const float* W = We + l * 4096;   // [32 k][128 n]
    float w0 = W[(k0 + 0) * 128 + n];
    float w1 = W[(k0 + 1) * 128 + n];
    float w2 = W[(k0 + 8) * 128 + n];
    float w3 = W[(k0 + 9) * 128 + n];
    g_Bfrag[i] = (part == 0)
        ? make_uint2(hilo_hi(w0, w1), hilo_hi(w2, w3))
        : make_uint2(hilo_lo(w0, w1), hilo_lo(w2, w3));
}

__global__ void w1prep_kernel(const float* __restrict__ W1) {
    int i = blockIdx.x * blockDim.x + threadIdx.x;
    if (i >= 4 * 2 * 8 * 32 * 32) return;
    int lane = i & 31;
    int nt   = (i >> 5) & 31;
    int ks   = (i >> 10) & 7;
    int part = (i >> 13) & 1;
    int l    = i >> 14;
    int t = lane & 3, g = lane >> 2;
    int n = nt * 8 + g;
    int k0 = ks * 16 + 2 * t;
    const float* W = W1 + (size_t)l * 128 * 256;   // [128 k][256 n]
    float w0 = W[(k0 + 0) * 256 + n];
    float w1 = W[(k0 + 1) * 256 + n];
    float w2 = W[(k0 + 8) * 256 + n];
    float w3 = W[(k0 + 9) * 256 + n];
    g_W1frag[i] = (part == 0)
        ? make_uint2(hilo_hi(w0, w1), hilo_hi(w2, w3))
        : make_uint2(hilo_lo(w0, w1), hilo_lo(w2, w3));
}

__global__ void w2prep_kernel(const float* __restrict__ W2) {
    int i = blockIdx.x * blockDim.x + threadIdx.x;
    if (i >= 4 * 2 * 16 * 16 * 32) return;
    int lane = i & 31;
    int nt   = (i >> 5) & 15;
    int ks   = (i >> 9) & 15;
    int part = (i >> 13) & 1;
    int l    = i >> 14;
    int t = lane & 3, g = lane >> 2;
    int n = nt * 8 + g;
    int k0 = ks * 16 + 2 * t;
    const float* W = W2 + (size_t)l * 256 * 128;   // [256 k][128 n]
    float w0 = W[(k0 + 0) * 128 + n];
    float w1 = W[(k0 + 1) * 128 + n];
    float w2 = W[(k0 + 8) * 128 + n];
    float w3 = W[(k0 + 9) * 128 + n];
    g_W2frag[i] = (part == 0)
        ? make_uint2(hilo_hi(w0, w1), hilo_hi(w2, w3))
        : make_uint2(hilo_lo(w0, w1), hilo_lo(w2, w3));
}

// ---------- Fused edge GEMM + aggregation ----------
// Block = 128 CSR rows, 256 threads. GEMM E=ea[perm]@We on tensor pipe;
// Msg = relu(x[src] + E + be) built in smem; segmented CSR reduction to agg.
// Dyn smem: Msg[128][132] f32 (67584) | Ah bf16[128*40] (10240) | Al (10240) = 88064
#define A_STRIDE 40
#define MSG_S 132
#define EF_SMEM (67584 + 10240 + 10240)

__global__ void __launch_bounds__(256, 2) edge_fused_kernel(
    const float* __restrict__ ea, const float* __restrict__ x,
    const uint2* __restrict__ bfh, const uint2* __restrict__ bfl,
    const float* __restrict__ be, float* __restrict__ agg,
    int nE, int nNodes)
{
    extern __shared__ char smc[];
    float* Msg = (float*)smc;
    __nv_bfloat16* Ah = (__nv_bfloat16*)(smc + 67584);
    __nv_bfloat16* Al = (__nv_bfloat16*)(smc + 77824);
    __shared__ int sperm[128];
    __shared__ int ssrc[128];

    int tid = threadIdx.x;
    int w = tid >> 5, lane = tid & 31;
    int base = blockIdx.x * 128;

    if (tid < 128) {
        int pos = base + tid;
        sperm[tid] = (pos < nE) ? g_perm[pos] : 0;
        ssrc[tid]  = (pos < nE) ? g_srcs[pos] : 0;
    }
    __syncthreads();

    // stage A tiles (ea rows, bf16 hi/lo)
    {
        int r = tid >> 1, half = tid & 1;
        const float4* row4 = (const float4*)(ea + (size_t)sperm[r] * 32) + half * 4;
#pragma unroll
        for (int j = 0; j < 4; j++) {
            float4 v = row4[j];
            int c = half * 16 + j * 4;
            *(uint2*)&Ah[r * A_STRIDE + c] = make_uint2(hilo_hi(v.x, v.y), hilo_hi(v.z, v.w));
            *(uint2*)&Al[r * A_STRIDE + c] = make_uint2(hilo_lo(v.x, v.y), hilo_lo(v.z, v.w));
        }
    }
    __syncthreads();

    // A fragments
    uint32_t ah[2][4], al[2][4];
    {
        uint32_t sAh = smem_u32(Ah), sAl = smem_u32(Al);
        int row = w * 16 + (lane & 15);
        int coff = ((lane >> 4) & 1) * 8;
#pragma unroll
        for (int ks = 0; ks < 2; ks++) {
            uint32_t off = (uint32_t)((row * A_STRIDE + coff + ks * 16) * 2);
            ldmatrix_x4(ah[ks][0], ah[ks][1], ah[ks][2], ah[ks][3], sAh + off);
            ldmatrix_x4(al[ks][0], al[ks][1], al[ks][2], al[ks][3], sAl + off);
        }
    }

    // stage Msg = x[src] + be (overlaps with MMA issue below)
    {
        int r = tid >> 1, half = tid & 1;
        const float4* xr = (const float4*)(x + (size_t)ssrc[r] * 128) + half * 16;
        const float4* be4 = (const float4*)be + half * 16;
        float* dst = Msg + r * MSG_S + half * 64;
#pragma unroll
        for (int j = 0; j < 16; j++) {
            float4 v = xr[j], b = be4[j];
            *(float4*)(dst + j * 4) = make_float4(v.x + b.x, v.y + b.y, v.z + b.z, v.w + b.w);
        }
    }

    // GEMM
    float acc[16][4];
#pragma unroll
    for (int nt = 0; nt < 16; nt++)
#pragma unroll
        for (int j = 0; j < 4; j++) acc[nt][j] = 0.f;

#pragma unroll
    for (int nt = 0; nt < 16; nt++) {
        uint2 bh0 = bfh[(nt * 2 + 0) * 32 + lane];
        uint2 bh1 = bfh[(nt * 2 + 1) * 32 + lane];
        uint2 bl0 = bfl[(nt * 2 + 0) * 32 + lane];
        uint2 bl1 = bfl[(nt * 2 + 1) * 32 + lane];
        mma_bf16(acc[nt], ah[0], bh0);
        mma_bf16(acc[nt], ah[1], bh1);
        mma_bf16(acc[nt], al[0], bh0);
        mma_bf16(acc[nt], al[1], bh1);
        mma_bf16(acc[nt], ah[0], bl0);
        mma_bf16(acc[nt], ah[1], bl1);
    }
    __syncthreads();

    // fragment add + relu into Msg
    {
        int g = lane >> 2, t = lane & 3;
        int r0 = w * 16 + g, r1 = r0 + 8;
#pragma unroll
        for (int nt = 0; nt < 16; nt++) {
            int c = nt * 8 + 2 * t;
            float* m0 = Msg + r0 * MSG_S + c;
            float* m1 = Msg + r1 * MSG_S + c;
            float2 v0 = *(float2*)m0;
            float2 v1 = *(float2*)m1;
            *(float2*)m0 = make_float2(fmaxf(v0.x + acc[nt][0], 0.f),
                                       fmaxf(v0.y + acc[nt][1], 0.f));
            *(float2*)m1 = make_float2(fmaxf(v1.x + acc[nt][2], 0.f),
                                       fmaxf(v1.y + acc[nt][3], 0.f));
        }
    }
    __syncthreads();

    // segmented reduction over CSR nodes covered by this tile (warp per segment)
    {
        int lastpos = min(base + 127, nE - 1);
        int n0 = g_pnode[base], n1 = g_pnode[lastpos];
        int limit = nE - base;
        for (int s = n0 + w; s <= n1; s += 8) {
            int os = g_off[s], oe = g_off[s + 1];
            int rs = max(os - base, 0);
            int re = min(min(oe - base, 128), limit);
            float4 sum = make_float4(0.f, 0.f, 0.f, 0.f);
            const float* mrow = Msg + rs * MSG_S + lane * 4;
            for (int r = rs; r < re; r++) {
                float4 v = *(const float4*)mrow;
                sum.x += v.x; sum.y += v.y; sum.z += v.z; sum.w += v.w;
                mrow += MSG_S;
            }
            float* dst = agg + (size_t)s * 128 + lane * 4;
            if (os >= base && oe <= base + 128) {
                *(float4*)dst = sum;
            } else {
                red4(dst, sum.x, sum.y, sum.z, sum.w);
            }
        }
    }
}

// ---------- Tensor-core MLP (unchanged from R14) ----------
#define MAS 136
#define MLP2_SMEM (34816 * 2 + 1024 + 512 * 3)

__global__ void __launch_bounds__(256, 1) mlp_mma_kernel(
    const float* __restrict__ xin, const float* __restrict__ agg,
    const uint2* __restrict__ w1h, const uint2* __restrict__ w1l,
    const uint2* __restrict__ w2h, const uint2* __restrict__ w2l,
    const float* __restrict__ b1, const float* __restrict__ b2,
    const float* __restrict__ lnw, const float* __restrict__ lnb,
    float* __restrict__ xout, int nNodes)
{
    extern __shared__ char smc[];
    __nv_bfloat16* Ah = (__nv_bfloat16*)smc;
    __nv_bfloat16* Al = (__nv_bfloat16*)(smc + 34816);
    float* b1s  = (float*)(smc + 69632);
    float* b2s  = b1s + 256;
    float* lnws = b2s + 128;
    float* lnbs = lnws + 128;

    int tid = threadIdx.x;
    int w = tid >> 5, lane = tid & 31;
    int g = lane >> 2, t = lane & 3;
    int m0 = blockIdx.x * 128;

    b1s[tid] = b1[tid];
    if (tid < 128) { b2s[tid] = b2[tid]; lnws[tid] = lnw[tid]; lnbs[tid] = lnb[tid]; }

    {
        const float4* x4 = (const float4*)xin;
        const float4* a4 = (const float4*)agg;
#pragma unroll
        for (int it = 0; it < 16; it++) {
            int idx = tid + it * 256;
            int r = idx >> 5, c4 = idx & 31;
            int gn = m0 + r;
            float4 v = make_float4(0.f, 0.f, 0.f, 0.f);
            if (gn < nNodes) {
                float4 a = x4[(size_t)gn * 32 + c4];
                float4 b = a4[(size_t)gn * 32 + c4];
                v = make_float4(a.x + b.x, a.y + b.y, a.z + b.z, a.w + b.w);
            }
            *(uint2*)&Ah[r * MAS + c4 * 4] = make_uint2(hilo_hi(v.x, v.y), hilo_hi(v.z, v.w));
            *(uint2*)&Al[r * MAS + c4 * 4] = make_uint2(hilo_lo(v.x, v.y), hilo_lo(v.z, v.w));
        }
    }
    __syncthreads();

    float acc[32][4];
#pragma unroll
    for (int nt = 0; nt < 32; nt++)
#pragma unroll
        for (int j = 0; j < 4; j++) acc[nt][j] = 0.f;

    {
        uint32_t sAh = smem_u32(Ah), sAl = smem_u32(Al);
        int row = w * 16 + (lane & 15);
        int coff = ((lane >> 4) & 1) * 8;
        uint32_t abase = (uint32_t)((row * MAS + coff) * 2);
        for (int ks = 0; ks < 8; ks++) {
            uint32_t ah[4], al[4];
            ldmatrix_x4(ah[0], ah[1], ah[2], ah[3], sAh + abase + ks * 32);
            ldmatrix_x4(al[0], al[1], al[2], al[3], sAl + abase + ks * 32);
            const uint2* ph = w1h + (ks * 32) * 32 + lane;
            const uint2* pl = w1l + (ks * 32) * 32 + lane;
#pragma unroll
            for (int nt = 0; nt < 32; nt++) {
                uint2 bh = ph[nt * 32];
                uint2 bl = pl[nt * 32];
                mma_bf16(acc[nt], ah, bh);
                mma_bf16(acc[nt], al, bh);
                mma_bf16(acc[nt], ah, bl);
            }
        }
    }

    uint32_t tfh[16][4], tfl[16][4];
#pragma unroll
    for (int ks2 = 0; ks2 < 16; ks2++) {
#pragma unroll
        for (int half = 0; half < 2; half++) {
            int nt = 2 * ks2 + half;
            float bb0 = b1s[nt * 8 + 2 * t], bb1 = b1s[nt * 8 + 2 * t + 1];
            float v0 = fmaxf(acc[nt][0] + bb0, 0.f);
            float v1 = fmaxf(acc[nt][1] + bb1, 0.f);
            float v2 = fmaxf(acc[nt][2] + bb0, 0.f);
            float v3 = fmaxf(acc[nt][3] + bb1, 0.f);
            tfh[ks2][half * 2 + 0] = hilo_hi(v0, v1);
            tfh[ks2][half * 2 + 1] = hilo_hi(v2, v3);
            tfl[ks2][half * 2 + 0] = hilo_lo(v0, v1);
            tfl[ks2][half * 2 + 1] = hilo_lo(v2, v3);
        }
    }

    float acc2[16][4];
#pragma unroll
    for (int nt = 0; nt < 16; nt++)
#pragma unroll
        for (int j = 0; j < 4; j++) acc2[nt][j] = 0.f;

#pragma unroll
    for (int ks2 = 0; ks2 < 16; ks2++) {
        const uint2* ph = w2h + (ks2 * 16) * 32 + lane;
        const uint2* pl = w2l + (ks2 * 16) * 32 + lane;
#pragma unroll
        for (int nt = 0; nt < 16; nt++) {
            uint2 bh = ph[nt * 32];
            uint2 bl = pl[nt * 32];
            mma_bf16(acc2[nt], tfh[ks2], bh);
            mma_bf16(acc2[nt], tfl[ks2], bh);
            mma_bf16(acc2[nt], tfh[ks2], bl);
        }
    }

    {
#pragma unroll
        for (int nt = 0; nt < 16; nt++) {
            float bb0 = b2s[nt * 8 + 2 * t], bb1 = b2s[nt * 8 + 2 * t + 1];
            acc2[nt][0] += bb0; acc2[nt][1] += bb1;
            acc2[nt][2] += bb0; acc2[nt][3] += bb1;
        }
        float s0 = 0.f, s1 = 0.f;
#pragma unroll
        for (int nt = 0; nt < 16; nt++) {
            s0 += acc2[nt][0] + acc2[nt][1];
            s1 += acc2[nt][2] + acc2[nt][3];
        }
        s0 += __shfl_xor_sync(0xffffffffu, s0, 1);
        s0 += __shfl_xor_sync(0xffffffffu, s0, 2);
        s1 += __shfl_xor_sync(0xffffffffu, s1, 1);
        s1 += __shfl_xor_sync(0xffffffffu, s1, 2);
        float mu0 = s0 * (1.0f / 128.0f), mu1 = s1 * (1.0f / 128.0f);
        float q0 = 0.f, q1 = 0.f;
#pragma unroll
        for (int nt = 0; nt < 16; nt++) {
            float d0 = acc2[nt][0] - mu0, d1 = acc2[nt][1] - mu0;
            float d2 = acc2[nt][2] - mu1, d3 = acc2[nt][3] - mu1;
            q0 += d0 * d0 + d1 * d1;
            q1 += d2 * d2 + d3 * d3;
        }
        q0 += __shfl_xor_sync(0xffffffffu, q0, 1);
        q0 += __shfl_xor_sync(0xffffffffu, q0, 2);
        q1 += __shfl_xor_sync(0xffffffffu, q1, 1);
        q1 += __shfl_xor_sync(0xffffffffu, q1, 2);
        float inv0 = rsqrtf(q0 * (1.0f / 128.0f) + 1e-5f);
        float inv1 = rsqrtf(q1 * (1.0f / 128.0f) + 1e-5f);

        int row0 = m0 + w * 16 + g;
        int row1 = row0 + 8;
        bool in0 = row0 < nNodes, in1 = row1 < nNodes;
#pragma unroll
        for (int nt = 0; nt < 16; nt++) {
            int c = nt * 8 + 2 * t;
            float lw0 = lnws[c], lw1 = lnws[c + 1];
            float lb0 = lnbs[c], lb1 = lnbs[c + 1];
            if (in0) {
                float2 xr = *(const float2*)&xin[(size_t)row0 * 128 + c];
                float o0 = fmaxf((acc2[nt][0] - mu0) * inv0 * lw0 + lb0 + xr.x, 0.f);
                float o1 = fmaxf((acc2[nt][1] - mu0) * inv0 * lw1 + lb1 + xr.y, 0.f);
                *(float2*)&xout[(size_t)row0 * 128 + c] = make_float2(o0, o1);
            }
            if (in1) {
                float2 xr = *(const float2*)&xin[(size_t)row1 * 128 + c];
                float o2 = fmaxf((acc2[nt][2] - mu1) * inv1 * lw0 + lb0 + xr.x, 0.f);
                float o3 = fmaxf((acc2[nt][3] - mu1) * inv1 * lw1 + lb1 + xr.y, 0.f);
                *(float2*)&xout[(size_t)row1 * 128 + c] = make_float2(o2, o3);
            }
        }
    }
}

// ---------- Output projection: out = x @ Wout + bout ----------
__global__ void __launch_bounds__(256) proj_kernel(
    const float* __restrict__ x, const float* __restrict__ Wout,
    const float* __restrict__ bout, float* __restrict__ out, int nNodes)
{
    __shared__ float xs[64 * 132];
    __shared__ float ws[32 * 64];
    int tid = threadIdx.x, tx = tid & 15, ty = tid >> 4;
    int m0 = blockIdx.x * 64;

#pragma unroll
    for (int it = 0; it < 8; it++) {
        int t = tid + it * 256;
        int r = t >> 5, c4 = t & 31;
        int gn = m0 + r;
        float4 v = make_float4(0.f, 0.f, 0.f, 0.f);
        if (gn < nNodes) v = ((const float4*)x)[(size_t)gn * 32 + c4];
        *(float4*)&xs[r * 132 + c4 * 4] = v;
    }

    unsigned long long acc[4][2];
#pragma unroll
    for (int i = 0; i < 4; i++) { acc[i][0] = 0ull; acc[i][1] = 0ull; }

    for (int kc = 0; kc < 4; kc++) {
#pragma unroll
        for (int it = 0; it < 2; it++) {
            int t = tid + it * 256;
            int kk = t >> 4, c4 = t & 15;
            *(float4*)&ws[kk * 64 + c4 * 4] =
                *(const float4*)&Wout[(size_t)(kc * 32 + kk) * 64 + c4 * 4];
        }
        __syncthreads();
#pragma unroll 8
        for (int kk = 0; kk < 32; kk++) {
            int k = kc * 32 + kk;
            ulonglong2 w = *(const ulonglong2*)&ws[kk * 64 + tx * 4];
#pragma unroll
            for (int i = 0; i < 4; i++) {
                float a = xs[(ty * 4 + i) * 132 + k];
                unsigned long long aa = pack2(a, a);
                acc[i][0] = fma2(aa, w.x, acc[i][0]);
                acc[i][1] = fma2(aa, w.y, acc[i][1]);
            }
        }
        __syncthreads();
    }

    float4 bv = *(const float4*)&bout[tx * 4];
#pragma unroll
    for (int i = 0; i < 4; i++) {
        int gn = m0 + ty * 4 + i;
        if (gn < nNodes) {
            float2 p0 = unpack2(acc[i][0]), p1 = unpack2(acc[i][1]);
            float4 o = make_float4(p0.x + bv.x, p0.y + bv.y, p1.x + bv.z, p1.y + bv.w);
            *(float4*)&out[(size_t)gn * 64 + tx * 4] = o;
        }
    }
}

extern "C" void kernel_launch(void* const* d_in, const int* in_sizes, int n_in,
                              void* d_out, int out_size) {
    const float* x        = (const float*)d_in[0];
    const void*  ei       = (const void*)d_in[1];
    const float* ea       = (const float*)d_in[2];
    const float* We       = (const float*)d_in[3];
    const float* be       = (const float*)d_in[4];
    const float* W1       = (const float*)d_in[5];
    const float* b1       = (const float*)d_in[6];
    const float* W2       = (const float*)d_in[7];
    const float* b2       = (const float*)d_in[8];
    const float* lnw      = (const float*)d_in[9];
    const float* lnb      = (const float*)d_in[10];
    const float* Wout     = (const float*)d_in[11];
    const float* bout     = (const float*)d_in[12];
    float* out            = (float*)d_out;

    int nNodes = in_sizes[0] / CH;
    int nEdges = in_sizes[1] / 2;

    float *xb0, *xb1, *agg;
    int *cnt;
    uint2 *bfrag, *w1f, *w2f;
    cudaGetSymbolAddress((void**)&xb0, g_x0);
    cudaGetSymbolAddress((void**)&xb1, g_x1);
    cudaGetSymbolAddress((void**)&agg, g_agg);
    cudaGetSymbolAddress((void**)&cnt, g_cnt);
    cudaGetSymbolAddress((void**)&bfrag, g_Bfrag);
    cudaGetSymbolAddress((void**)&w1f, g_W1frag);
    cudaGetSymbolAddress((void**)&w2f, g_W2frag);

    cudaFuncSetAttribute(mlp_mma_kernel, cudaFuncAttributeMaxDynamicSharedMemorySize, MLP2_SMEM);
    cudaFuncSetAttribute(edge_fused_kernel, cudaFuncAttributeMaxDynamicSharedMemorySize, EF_SMEM);

    int eb = (nEdges + 255) / 256;
    int nb = (nNodes + 255) / 256;

    detect_kernel<<<1, 32>>>((const unsigned int*)ei);
    convert_kernel<<<256, 256>>>(ei, nEdges);

    cudaMemsetAsync(cnt, 0, (size_t)nNodes * sizeof(int), 0);
    hist_kernel<<<eb, 256>>>(nEdges);
    scanA_kernel<<<nb, 256>>>(nNodes);
    scanB_kernel<<<1, 512>>>(nb);
    scanC_kernel<<<nb, 256>>>(nNodes);
    cudaMemsetAsync(cnt, 0, (size_t)nNodes * sizeof(int), 0);
    scatter_kernel<<<eb, 256>>>(nEdges);
    sortrow_kernel<<<nb, 256>>>(nNodes);
    srcs_kernel<<<eb, 256>>>(nEdges);
    pnode_kernel<<<eb, 256>>>(nEdges, nNodes);
    bprep_kernel<<<32, 256>>>(We);
    w1prep_kernel<<<256, 256>>>(W1);
    w2prep_kernel<<<256, 256>>>(W2);

    int fusedBlocks = (nEdges + 127) / 128;
    int mlpBlocks   = (nNodes + 127) / 128;
    int projBlocks  = (nNodes + 63) / 64;
    const float* cur = x;
    for (int l = 0; l < 4; l++) {
        float* nxt = (l & 1) ? xb1 : xb0;
        const uint2* bfh = bfrag + (l * 2 + 0) * 1024;
        const uint2* bfl = bfrag + (l * 2 + 1) * 1024;
        const uint2* w1h = w1f + (l * 2 + 0) * 8192;
        const uint2* w1l = w1f + (l * 2 + 1) * 8192;
        const uint2* w2h = w2f + (l * 2 + 0) * 8192;
        const uint2* w2l = w2f + (l * 2 + 1) * 8192;
        cudaMemsetAsync(agg, 0, (size_t)nNodes * CH * sizeof(float), 0);
        edge_fused_kernel<<<fusedBlocks, 256, EF_SMEM>>>(
            ea, cur, bfh, bfl, be + (size_t)l * CH, agg, nEdges, nNodes);
        mlp_mma_kernel<<<mlpBlocks, 256, MLP2_SMEM>>>(
            cur, agg, w1h, w1l, w2h, w2l,
            b1 + (size_t)l * 256, b2 + (size_t)l * CH,
            lnw + (size_t)l * CH, lnb + (size_t)l * CH, nxt, nNodes);
        cur = nxt;
    }
    proj_kernel<<<projBlocks, 256>>>(cur, Wout, bout, out, nNodes);
}

// round 16
// speedup vs baseline: 1.3073x; 1.3073x over previous
#include <cuda_runtime.h>
#include <cuda_bf16.h>
#include <cuda_fp16.h>
#include <cstdint>
#include <cstddef>

#define NN_MAX 100000
#define NE_MAX 1600000
#define CH 128

// Scratch (static __device__ allocation is the sanctioned workaround)
__device__ float g_x0[(size_t)NN_MAX * CH];
__device__ float g_x1[(size_t)NN_MAX * CH];
__device__ float g_agg[(size_t)NN_MAX * CH];
__device__ int2  g_epk[(size_t)NE_MAX];
__device__ int   g_is64;
// CSR structures (dst is layer-invariant; built once per launch)
__device__ int   g_cnt[NN_MAX];
__device__ int   g_off[NN_MAX + 1];
__device__ int   g_part[512];
__device__ int   g_perm[NE_MAX];
__device__ int   g_srcs[NE_MAX];
// Edge transform scratch (fp16: halves DRAM round-trip vs fp32)
__device__ __half g_E[(size_t)NE_MAX * CH];
// Pre-packed B fragments for mma.m16n8k16:
__device__ uint2 g_Bfrag[4 * 2 * 16 * 2 * 32];          // We  [layer][part][nt16][ks2][lane]
__device__ uint2 g_W1frag[4 * 2 * 8 * 32 * 32];         // W1  [layer][part][ks8][nt32][lane]
__device__ uint2 g_W2frag[4 * 2 * 16 * 16 * 32];        // W2  [layer][part][ks16][nt16][lane]

// ---------- f32x2 helpers ----------
__device__ __forceinline__ unsigned long long pack2(float a, float b) {
    unsigned long long r;
    asm("mov.b64 %0, {%1, %2};" : "=l"(r) : "f"(a), "f"(b));
    return r;
}
__device__ __forceinline__ float2 unpack2(unsigned long long v) {
    float2 f;
    asm("mov.b64 {%0, %1}, %2;" : "=f"(f.x), "=f"(f.y) : "l"(v));
    return f;
}
__device__ __forceinline__ unsigned long long fma2(unsigned long long a,
                                                   unsigned long long b,
                                                   unsigned long long c) {
    unsigned long long d;
    asm("fma.rn.f32x2 %0, %1, %2, %3;" : "=l"(d) : "l"(a), "l"(b), "l"(c));
    return d;
}

// ---------- mma.sync helpers (baseline PTX; works on plain sm_103 target) ----------
__device__ __forceinline__ uint32_t smem_u32(const void* p) {
    uint32_t a;
    asm("{ .reg .u64 t; cvta.to.shared.u64 t, %1; cvt.u32.u64 %0, t; }" : "=r"(a) : "l"(p));
    return a;
}
__device__ __forceinline__ void ldmatrix_x4(uint32_t& r0, uint32_t& r1,
                                            uint32_t& r2, uint32_t& r3, uint32_t addr) {
    asm volatile("ldmatrix.sync.aligned.m8n8.x4.shared.b16 {%0,%1,%2,%3}, [%4];"
                 : "=r"(r0), "=r"(r1), "=r"(r2), "=r"(r3) : "r"(addr));
}
__device__ __forceinline__ void mma_bf16(float* c, const uint32_t* a, uint2 b) {
    asm volatile("mma.sync.aligned.m16n8k16.row.col.f32.bf16.bf16.f32 "
                 "{%0,%1,%2,%3}, {%4,%5,%6,%7}, {%8,%9}, {%0,%1,%2,%3};"
                 : "+f"(c[0]), "+f"(c[1]), "+f"(c[2]), "+f"(c[3])
                 : "r"(a[0]), "r"(a[1]), "r"(a[2]), "r"(a[3]), "r"(b.x), "r"(b.y));
}
__device__ __forceinline__ uint32_t pack_bf16(__nv_bfloat16 lo, __nv_bfloat16 hi) {
    uint16_t l = *(uint16_t*)&lo, h = *(uint16_t*)&hi;
    return (uint32_t)l | ((uint32_t)h << 16);
}
__device__ __forceinline__ uint32_t hilo_hi(float a, float b) {
    return pack_bf16(__float2bfloat16(a), __float2bfloat16(b));
}
__device__ __forceinline__ uint32_t hilo_lo(float a, float b) {
    __nv_bfloat16 ha = __float2bfloat16(a), hb = __float2bfloat16(b);
    return pack_bf16(__float2bfloat16(a - __bfloat162float(ha)),
                     __float2bfloat16(b - __bfloat162float(hb)));
}

// ---------- dtype detection + index canonicalization ----------
__global__ void detect_kernel(const unsigned int* e32) {
    if (threadIdx.x == 0 && blockIdx.x == 0) {
        int is64 = 1;
        for (int i = 0; i < 256; i += 2)
            if (e32[i + 1] != 0u) is64 = 0;
        g_is64 = is64;
    }
}

__global__ void convert_kernel(const void* ei, int nE) {
    int f = g_is64;
    int i = blockIdx.x * blockDim.x + threadIdx.x;
    int stride = gridDim.x * blockDim.x;
    if (f) {
        const long long* p = (const long long*)ei;
        for (; i < nE; i += stride)
            g_epk[i] = make_int2((int)p[i], (int)p[nE + i]);
    } else {
        const int* p = (const int*)ei;
        for (; i < nE; i += stride)
            g_epk[i] = make_int2(p[i], p[nE + i]);
    }
}

// ---------- CSR build ----------
__global__ void hist_kernel(int nE) {
    int i = blockIdx.x * blockDim.x + threadIdx.x;
    if (i < nE) atomicAdd(&g_cnt[g_epk[i].y], 1);
}

__global__ void scanA_kernel(int n) {
    __shared__ int sd[256];
    int tid = threadIdx.x;
    int i = blockIdx.x * 256 + tid;
    int v = (i < n) ? g_cnt[i] : 0;
    sd[tid] = v;
    __syncthreads();
    for (int d = 1; d < 256; d <<= 1) {
        int u = (tid >= d) ? sd[tid - d] : 0;
        __syncthreads();
        sd[tid] += u;
        __syncthreads();
    }
    if (i < n) g_off[i] = sd[tid] - v;
    if (tid == 255) g_part[blockIdx.x] = sd[255];
}
__global__ void __launch_bounds__(512) scanB_kernel(int nb) {
    __shared__ int sd[512];
    int tid = threadIdx.x;
    int v = (tid < nb) ? g_part[tid] : 0;
    sd[tid] = v;
    __syncthreads();
    for (int d = 1; d < 512; d <<= 1) {
        int u = (tid >= d) ? sd[tid - d] : 0;
        __syncthreads();
        sd[tid] += u;
        __syncthreads();
    }
    if (tid < nb) g_part[tid] = sd[tid] - v;
}
__global__ void scanC_kernel(int n) {
    int i = blockIdx.x * 256 + threadIdx.x;
    if (i < n) {
        int o = g_off[i] + g_part[blockIdx.x];
        g_off[i] = o;
        if (i == n - 1) g_off[n] = o + g_cnt[i];
    }
}

__global__ void scatter_kernel(int nE) {
    int e = blockIdx.x * blockDim.x + threadIdx.x;
    if (e < nE) {
        int d = g_epk[e].y;
        int pos = g_off[d] + atomicAdd(&g_cnt[d], 1);
        g_perm[pos] = e;
    }
}

__global__ void sortrow_kernel(int nNodes) {
    int n = blockIdx.x * blockDim.x + threadIdx.x;
    if (n >= nNodes) return;
    int s = g_off[n], e = g_off[n + 1];
    int deg = e - s;
    if (deg <= 1) return;
    if (deg <= 64) {
        int a[64];
        for (int i = 0; i < deg; i++) a[i] = g_perm[s + i];
        for (int i = 1; i < deg; i++) {
            int v = a[i], j = i - 1;
            while (j >= 0 && a[j] > v) { a[j + 1] = a[j]; j--; }
            a[j + 1] = v;
        }
        for (int i = 0; i < deg; i++) g_perm[s + i] = a[i];
    } else {
        for (int i = s + 1; i < e; i++) {
            int v = g_perm[i], j = i - 1;
            while (j >= s && g_perm[j] > v) { g_perm[j + 1] = g_perm[j]; j--; }
            g_perm[j + 1] = v;
        }
    }
}

__global__ void srcs_kernel(int nE) {
    int p = blockIdx.x * blockDim.x + threadIdx.x;
    if (p < nE) g_srcs[p] = g_epk[g_perm[p]].x;
}

// ---------- B-fragment prep ----------
__global__ void bprep_kernel(const float* __restrict__ We) {
    int i = blockIdx.x * blockDim.x + threadIdx.x;
    if (i >= 4 * 2 * 16 * 2 * 32) return;
    int lane = i & 31;
    int ks   = (i >> 5) & 1;
    int nt   = (i >> 6) & 15;
    int part = (i >> 10) & 1;
    int l    = i >> 11;
    int t = lane & 3, g = lane >> 2;
    int n = nt * 8 + g;
    int k0 = ks * 16 + 2 * t;
    const float* W = We + l * 4096;   // [32 k][128 n]
    float w0 = W[(k0 + 0) * 128 + n];
    float w1 = W[(k0 + 1) * 128 + n];
    float w2 = W[(k0 + 8) * 128 + n];
    float w3 = W[(k0 + 9) * 128 + n];
    g_Bfrag[i] = (part == 0)
        ? make_uint2(hilo_hi(w0, w1), hilo_hi(w2, w3))
        : make_uint2(hilo_lo(w0, w1), hilo_lo(w2, w3));
}

__global__ void w1prep_kernel(const float* __restrict__ W1) {
    int i = blockIdx.x * blockDim.x + threadIdx.x;
    if (i >= 4 * 2 * 8 * 32 * 32) return;
    int lane = i & 31;
    int nt   = (i >> 5) & 31;
    int ks   = (i >> 10) & 7;
    int part = (i >> 13) & 1;
    int l    = i >> 14;
    int t = lane & 3, g = lane >> 2;
    int n = nt * 8 + g;
    int k0 = ks * 16 + 2 * t;
    const float* W = W1 + (size_t)l * 128 * 256;   // [128 k][256 n]
    float w0 = W[(k0 + 0) * 256 + n];
    float w1 = W[(k0 + 1) * 256 + n];
    float w2 = W[(k0 + 8) * 256 + n];
    float w3 = W[(k0 + 9) * 256 + n];
    g_W1frag[i] = (part == 0)
        ? make_uint2(hilo_hi(w0, w1), hilo_hi(w2, w3))
        : make_uint2(hilo_lo(w0, w1), hilo_lo(w2, w3));
}

__global__ void w2prep_kernel(const float* __restrict__ W2) {
    int i = blockIdx.x * blockDim.x + threadIdx.x;
    if (i >= 4 * 2 * 16 * 16 * 32) return;
    int lane = i & 31;
    int nt   = (i >> 5) & 15;
    int ks   = (i >> 9) & 15;
    int part = (i >> 13) & 1;
    int l    = i >> 14;
    int t = lane & 3, g = lane >> 2;
    int n = nt * 8 + g;
    int k0 = ks * 16 + 2 * t;
    const float* W = W2 + (size_t)l * 256 * 128;   // [256 k][128 n]
    float w0 = W[(k0 + 0) * 128 + n];
    float w1 = W[(k0 + 1) * 128 + n];
    float w2 = W[(k0 + 8) * 128 + n];
    float w3 = W[(k0 + 9) * 128 + n];
    g_W2frag[i] = (part == 0)
        ? make_uint2(hilo_hi(w0, w1), hilo_hi(w2, w3))
        : make_uint2(hilo_lo(w0, w1), hilo_lo(w2, w3));
}

// ---------- Edge GEMM: E[pos][:] = ea[perm[pos]][:] @ We  (mma.sync bf16 hi/lo x3) ----------
#define A_STRIDE 40

__global__ void __launch_bounds__(256) edge_gemm_kernel(
    const float* __restrict__ ea,
    const uint2* __restrict__ bfh, const uint2* __restrict__ bfl,
    __half* __restrict__ E, int nE)
{
    __shared__ __nv_bfloat16 Ah[128 * A_STRIDE];
    __shared__ __nv_bfloat16 Al[128 * A_STRIDE];
    __shared__ int sperm[128];

    int tid = threadIdx.x;
    int w = tid >> 5, lane = tid & 31;
    int base = blockIdx.x * 128;

    if (tid < 128) {
        int pos = base + tid;
        sperm[tid] = (pos < nE) ? g_perm[pos] : 0;
    }
    __syncthreads();

    {
        int r = tid >> 1, half = tid & 1;
        const float4* row4 = (const float4*)(ea + (size_t)sperm[r] * 32) + half * 4;
#pragma unroll
        for (int j = 0; j < 4; j++) {
            float4 v = row4[j];
            int c = half * 16 + j * 4;
            *(uint2*)&Ah[r * A_STRIDE + c] = make_uint2(hilo_hi(v.x, v.y), hilo_hi(v.z, v.w));
            *(uint2*)&Al[r * A_STRIDE + c] = make_uint2(hilo_lo(v.x, v.y), hilo_lo(v.z, v.w));
        }
    }
    __syncthreads();

    uint32_t ah[2][4], al[2][4];
    {
        uint32_t sAh = smem_u32(Ah), sAl = smem_u32(Al);
        int row = w * 16 + (lane & 15);
        int coff = ((lane >> 4) & 1) * 8;
#pragma unroll
        for (int ks = 0; ks < 2; ks++) {
            uint32_t off = (uint32_t)((row * A_STRIDE + coff + ks * 16) * 2);
            ldmatrix_x4(ah[ks][0], ah[ks][1], ah[ks][2], ah[ks][3], sAh + off);
            ldmatrix_x4(al[ks][0], al[ks][1], al[ks][2], al[ks][3], sAl + off);
        }
    }

    float acc[16][4];
#pragma unroll
    for (int nt = 0; nt < 16; nt++)
#pragma unroll
        for (int j = 0; j < 4; j++) acc[nt][j] = 0.f;

#pragma unroll
    for (int nt = 0; nt < 16; nt++) {
        uint2 bh0 = bfh[(nt * 2 + 0) * 32 + lane];
        uint2 bh1 = bfh[(nt * 2 + 1) * 32 + lane];
        uint2 bl0 = bfl[(nt * 2 + 0) * 32 + lane];
        uint2 bl1 = bfl[(nt * 2 + 1) * 32 + lane];
        mma_bf16(acc[nt], ah[0], bh0);
        mma_bf16(acc[nt], ah[1], bh1);
        mma_bf16(acc[nt], al[0], bh0);
        mma_bf16(acc[nt], al[1], bh1);
        mma_bf16(acc[nt], ah[0], bl0);
        mma_bf16(acc[nt], ah[1], bl1);
    }

    {
        int g = lane >> 2, t = lane & 3;
        int pos0 = base + w * 16 + g;
        int pos1 = pos0 + 8;
        bool in0 = pos0 < nE, in1 = pos1 < nE;
        __half* e0 = E + (size_t)pos0 * 128 + 2 * t;
        __half* e1 = E + (size_t)pos1 * 128 + 2 * t;
#pragma unroll
        for (int nt = 0; nt < 16; nt++) {
            if (in0) *(__half2*)(e0 + nt * 8) = __floats2half2_rn(acc[nt][0], acc[nt][1]);
            if (in1) *(__half2*)(e1 + nt * 8) = __floats2half2_rn(acc[nt][2], acc[nt][3]);
        }
    }
}

// ---------- Aggregation: agg[n] = sum_p relu(x[src_p] + E_p + be)  (1 warp/node) ----------
__global__ void __launch_bounds__(256) agg_kernel(
    const float* __restrict__ x, const __half* __restrict__ E,
    const float* __restrict__ be, float* __restrict__ agg, int nNodes)
{
    int lane = threadIdx.x & 31;
    int n = blockIdx.x * 8 + (threadIdx.x >> 5);
    if (n >= nNodes) return;
    int c0 = lane * 4;
    float4 bias = *(const float4*)&be[c0];
    float4 acc = make_float4(0.f, 0.f, 0.f, 0.f);
    int ps = g_off[n], pe = g_off[n + 1];
    for (int p = ps; p < pe; p++) {
        int src = g_srcs[p];
        uint2 epk = *(const uint2*)(E + (size_t)p * 128 + c0);
        float2 e0 = __half22float2(*(__half2*)&epk.x);
        float2 e1 = __half22float2(*(__half2*)&epk.y);
        float4 x4 = *(const float4*)&x[(size_t)src * 128 + c0];
        acc.x += fmaxf(x4.x + e0.x + bias.x, 0.f);
        acc.y += fmaxf(x4.y + e0.y + bias.y, 0.f);
        acc.z += fmaxf(x4.z + e1.x + bias.z, 0.f);
        acc.w += fmaxf(x4.w + e1.y + bias.w, 0.f);
    }
    *(float4*)&agg[(size_t)n * 128 + c0] = acc;
}

// ---------- Tensor-core MLP ----------
#define MAS 136
#define MLP2_SMEM (34816 * 2 + 1024 + 512 * 3)

__global__ void __launch_bounds__(256, 1) mlp_mma_kernel(
    const float* __restrict__ xin, const float* __restrict__ agg,
    const uint2* __restrict__ w1h, const uint2* __restrict__ w1l,
    const uint2* __restrict__ w2h, const uint2* __restrict__ w2l,
    const float* __restrict__ b1, const float* __restrict__ b2,
    const float* __restrict__ lnw, const float* __restrict__ lnb,
    float* __restrict__ xout, int nNodes)
{
    extern __shared__ char smc[];
    __nv_bfloat16* Ah = (__nv_bfloat16*)smc;
    __nv_bfloat16* Al = (__nv_bfloat16*)(smc + 34816);
    float* b1s  = (float*)(smc + 69632);
    float* b2s  = b1s + 256;
    float* lnws = b2s + 128;
    float* lnbs = lnws + 128;

    int tid = threadIdx.x;
    int w = tid >> 5, lane = tid & 31;
    int g = lane >> 2, t = lane & 3;
    int m0 = blockIdx.x * 128;

    b1s[tid] = b1[tid];
    if (tid < 128) { b2s[tid] = b2[tid]; lnws[tid] = lnw[tid]; lnbs[tid] = lnb[tid]; }

    {
        const float4* x4 = (const float4*)xin;
        const float4* a4 = (const float4*)agg;
#pragma unroll
        for (int it = 0; it < 16; it++) {
            int idx = tid + it * 256;
            int r = idx >> 5, c4 = idx & 31;
            int gn = m0 + r;
            float4 v = make_float4(0.f, 0.f, 0.f, 0.f);
            if (gn < nNodes) {
                float4 a = x4[(size_t)gn * 32 + c4];
                float4 b = a4[(size_t)gn * 32 + c4];
                v = make_float4(a.x + b.x, a.y + b.y, a.z + b.z, a.w + b.w);
            }
            *(uint2*)&Ah[r * MAS + c4 * 4] = make_uint2(hilo_hi(v.x, v.y), hilo_hi(v.z, v.w));
            *(uint2*)&Al[r * MAS + c4 * 4] = make_uint2(hilo_lo(v.x, v.y), hilo_lo(v.z, v.w));
        }
    }
    __syncthreads();

    float acc[32][4];
#pragma unroll
    for (int nt = 0; nt < 32; nt++)
#pragma unroll
        for (int j = 0; j < 4; j++) acc[nt][j] = 0.f;

    {
        uint32_t sAh = smem_u32(Ah), sAl = smem_u32(Al);
        int row = w * 16 + (lane & 15);
        int coff = ((lane >> 4) & 1) * 8;
        uint32_t abase = (uint32_t)((row * MAS + coff) * 2);
        for (int ks = 0; ks < 8; ks++) {
            uint32_t ah[4], al[4];
            ldmatrix_x4(ah[0], ah[1], ah[2], ah[3], sAh + abase + ks * 32);
            ldmatrix_x4(al[0], al[1], al[2], al[3], sAl + abase + ks * 32);
            const uint2* ph = w1h + (ks * 32) * 32 + lane;
            const uint2* pl = w1l + (ks * 32) * 32 + lane;
#pragma unroll
            for (int nt = 0; nt < 32; nt++) {
                uint2 bh = ph[nt * 32];
                uint2 bl = pl[nt * 32];
                mma_bf16(acc[nt], ah, bh);
                mma_bf16(acc[nt], al, bh);
                mma_bf16(acc[nt], ah, bl);
            }
        }
    }

    uint32_t tfh[16][4], tfl[16][4];
#pragma unroll
    for (int ks2 = 0; ks2 < 16; ks2++) {
#pragma unroll
        for (int half = 0; half < 2; half++) {
            int nt = 2 * ks2 + half;
            float bb0 = b1s[nt * 8 + 2 * t], bb1 = b1s[nt * 8 + 2 * t + 1];
            float v0 = fmaxf(acc[nt][0] + bb0, 0.f);
            float v1 = fmaxf(acc[nt][1] + bb1, 0.f);
            float v2 = fmaxf(acc[nt][2] + bb0, 0.f);
            float v3 = fmaxf(acc[nt][3] + bb1, 0.f);
            tfh[ks2][half * 2 + 0] = hilo_hi(v0, v1);
            tfh[ks2][half * 2 + 1] = hilo_hi(v2, v3);
            tfl[ks2][half * 2 + 0] = hilo_lo(v0, v1);
            tfl[ks2][half * 2 + 1] = hilo_lo(v2, v3);
        }
    }

    float acc2[16][4];
#pragma unroll
    for (int nt = 0; nt < 16; nt++)
#pragma unroll
        for (int j = 0; j < 4; j++) acc2[nt][j] = 0.f;

#pragma unroll
    for (int ks2 = 0; ks2 < 16; ks2++) {
        const uint2* ph = w2h + (ks2 * 16) * 32 + lane;
        const uint2* pl = w2l + (ks2 * 16) * 32 + lane;
#pragma unroll
        for (int nt = 0; nt < 16; nt++) {
            uint2 bh = ph[nt * 32];
            uint2 bl = pl[nt * 32];
            mma_bf16(acc2[nt], tfh[ks2], bh);
            mma_bf16(acc2[nt], tfl[ks2], bh);
            mma_bf16(acc2[nt], tfh[ks2], bl);
        }
    }

    {
#pragma unroll
        for (int nt = 0; nt < 16; nt++) {
            float bb0 = b2s[nt * 8 + 2 * t], bb1 = b2s[nt * 8 + 2 * t + 1];
            acc2[nt][0] += bb0; acc2[nt][1] += bb1;
            acc2[nt][2] += bb0; acc2[nt][3] += bb1;
        }
        float s0 = 0.f, s1 = 0.f;
#pragma unroll
        for (int nt = 0; nt < 16; nt++) {
            s0 += acc2[nt][0] + acc2[nt][1];
            s1 += acc2[nt][2] + acc2[nt][3];
        }
        s0 += __shfl_xor_sync(0xffffffffu, s0, 1);
        s0 += __shfl_xor_sync(0xffffffffu, s0, 2);
        s1 += __shfl_xor_sync(0xffffffffu, s1, 1);
        s1 += __shfl_xor_sync(0xffffffffu, s1, 2);
        float mu0 = s0 * (1.0f / 128.0f), mu1 = s1 * (1.0f / 128.0f);
        float q0 = 0.f, q1 = 0.f;
#pragma unroll
        for (int nt = 0; nt < 16; nt++) {
            float d0 = acc2[nt][0] - mu0, d1 = acc2[nt][1] - mu0;
            float d2 = acc2[nt][2] - mu1, d3 = acc2[nt][3] - mu1;
            q0 += d0 * d0 + d1 * d1;
            q1 += d2 * d2 + d3 * d3;
        }
        q0 += __shfl_xor_sync(0xffffffffu, q0, 1);
        q0 += __shfl_xor_sync(0xffffffffu, q0, 2);
        q1 += __shfl_xor_sync(0xffffffffu, q1, 1);
        q1 += __shfl_xor_sync(0xffffffffu, q1, 2);
        float inv0 = rsqrtf(q0 * (1.0f / 128.0f) + 1e-5f);
        float inv1 = rsqrtf(q1 * (1.0f / 128.0f) + 1e-5f);

        int row0 = m0 + w * 16 + g;
        int row1 = row0 + 8;
        bool in0 = row0 < nNodes, in1 = row1 < nNodes;
#pragma unroll
        for (int nt = 0; nt < 16; nt++) {
            int c = nt * 8 + 2 * t;
            float lw0 = lnws[c], lw1 = lnws[c + 1];
            float lb0 = lnbs[c], lb1 = lnbs[c + 1];
            if (in0) {
                float2 xr = *(const float2*)&xin[(size_t)row0 * 128 + c];
                float o0 = fmaxf((acc2[nt][0] - mu0) * inv0 * lw0 + lb0 + xr.x, 0.f);
                float o1 = fmaxf((acc2[nt][1] - mu0) * inv0 * lw1 + lb1 + xr.y, 0.f);
                *(float2*)&xout[(size_t)row0 * 128 + c] = make_float2(o0, o1);
            }
            if (in1) {
                float2 xr = *(const float2*)&xin[(size_t)row1 * 128 + c];
                float o2 = fmaxf((acc2[nt][2] - mu1) * inv1 * lw0 + lb0 + xr.x, 0.f);
                float o3 = fmaxf((acc2[nt][3] - mu1) * inv1 * lw1 + lb1 + xr.y, 0.f);
                *(float2*)&xout[(size_t)row1 * 128 + c] = make_float2(o2, o3);
            }
        }
    }
}

// ---------- Output projection: out = x @ Wout + bout ----------
__global__ void __launch_bounds__(256) proj_kernel(
    const float* __restrict__ x, const float* __restrict__ Wout,
    const float* __restrict__ bout, float* __restrict__ out, int nNodes)
{
    __shared__ float xs[64 * 132];
    __shared__ float ws[32 * 64];
    int tid = threadIdx.x, tx = tid & 15, ty = tid >> 4;
    int m0 = blockIdx.x * 64;

#pragma unroll
    for (int it = 0; it < 8; it++) {
        int t = tid + it * 256;
        int r = t >> 5, c4 = t & 31;
        int gn = m0 + r;
        float4 v = make_float4(0.f, 0.f, 0.f, 0.f);
        if (gn < nNodes) v = ((const float4*)x)[(size_t)gn * 32 + c4];
        *(float4*)&xs[r * 132 + c4 * 4] = v;
    }

    unsigned long long acc[4][2];
#pragma unroll
    for (int i = 0; i < 4; i++) { acc[i][0] = 0ull; acc[i][1] = 0ull; }

    for (int kc = 0; kc < 4; kc++) {
#pragma unroll
        for (int it = 0; it < 2; it++) {
            int t = tid + it * 256;
            int kk = t >> 4, c4 = t & 15;
            *(float4*)&ws[kk * 64 + c4 * 4] =
                *(const float4*)&Wout[(size_t)(kc * 32 + kk) * 64 + c4 * 4];
        }
        __syncthreads();
#pragma unroll 8
        for (int kk = 0; kk < 32; kk++) {
            int k = kc * 32 + kk;
            ulonglong2 w = *(const ulonglong2*)&ws[kk * 64 + tx * 4];
#pragma unroll
            for (int i = 0; i < 4; i++) {
                float a = xs[(ty * 4 + i) * 132 + k];
                unsigned long long aa = pack2(a, a);
                acc[i][0] = fma2(aa, w.x, acc[i][0]);
                acc[i][1] = fma2(aa, w.y, acc[i][1]);
            }
        }
        __syncthreads();
    }

    float4 bv = *(const float4*)&bout[tx * 4];
#pragma unroll
    for (int i = 0; i < 4; i++) {
        int gn = m0 + ty * 4 + i;
        if (gn < nNodes) {
            float2 p0 = unpack2(acc[i][0]), p1 = unpack2(acc[i][1]);
            float4 o = make_float4(p0.x + bv.x, p0.y + bv.y, p1.x + bv.z, p1.y + bv.w);
            *(float4*)&out[(size_t)gn * 64 + tx * 4] = o;
        }
    }
}

extern "C" void kernel_launch(void* const* d_in, const int* in_sizes, int n_in,
                              void* d_out, int out_size) {
    const float* x        = (const float*)d_in[0];
    const void*  ei       = (const void*)d_in[1];
    const float* ea       = (const float*)d_in[2];
    const float* We       = (const float*)d_in[3];
    const float* be       = (const float*)d_in[4];
    const float* W1       = (const float*)d_in[5];
    const float* b1       = (const float*)d_in[6];
    const float* W2       = (const float*)d_in[7];
    const float* b2       = (const float*)d_in[8];
    const float* lnw      = (const float*)d_in[9];
    const float* lnb      = (const float*)d_in[10];
    const float* Wout     = (const float*)d_in[11];
    const float* bout     = (const float*)d_in[12];
    float* out            = (float*)d_out;

    int nNodes = in_sizes[0] / CH;
    int nEdges = in_sizes[1] / 2;

    float *xb0, *xb1, *agg;
    __half *Ebuf;
    int *cnt;
    uint2 *bfrag, *w1f, *w2f;
    cudaGetSymbolAddress((void**)&xb0, g_x0);
    cudaGetSymbolAddress((void**)&xb1, g_x1);
    cudaGetSymbolAddress((void**)&agg, g_agg);
    cudaGetSymbolAddress((void**)&cnt, g_cnt);
    cudaGetSymbolAddress((void**)&Ebuf, g_E);
    cudaGetSymbolAddress((void**)&bfrag, g_Bfrag);
    cudaGetSymbolAddress((void**)&w1f, g_W1frag);
    cudaGetSymbolAddress((void**)&w2f, g_W2frag);

    cudaFuncSetAttribute(mlp_mma_kernel, cudaFuncAttributeMaxDynamicSharedMemorySize, MLP2_SMEM);

    int eb = (nEdges + 255) / 256;
    int nb = (nNodes + 255) / 256;

    detect_kernel<<<1, 32>>>((const unsigned int*)ei);
    convert_kernel<<<256, 256>>>(ei, nEdges);

    cudaMemsetAsync(cnt, 0, (size_t)nNodes * sizeof(int), 0);
    hist_kernel<<<eb, 256>>>(nEdges);
    scanA_kernel<<<nb, 256>>>(nNodes);
    scanB_kernel<<<1, 512>>>(nb);
    scanC_kernel<<<nb, 256>>>(nNodes);
    cudaMemsetAsync(cnt, 0, (size_t)nNodes * sizeof(int), 0);
    scatter_kernel<<<eb, 256>>>(nEdges);
    sortrow_kernel<<<nb, 256>>>(nNodes);
    srcs_kernel<<<eb, 256>>>(nEdges);
    bprep_kernel<<<32, 256>>>(We);
    w1prep_kernel<<<256, 256>>>(W1);
    w2prep_kernel<<<256, 256>>>(W2);

    int gemmBlocks = (nEdges + 127) / 128;
    int aggBlocks  = (nNodes + 7) / 8;
    int mlpBlocks  = (nNodes + 127) / 128;
    int projBlocks = (nNodes + 63) / 64;
    const float* cur = x;
    for (int l = 0; l < 4; l++) {
        float* nxt = (l & 1) ? xb1 : xb0;
        const uint2* bfh = bfrag + (l * 2 + 0) * 1024;
        const uint2* bfl = bfrag + (l * 2 + 1) * 1024;
        const uint2* w1h = w1f + (l * 2 + 0) * 8192;
        const uint2* w1l = w1f + (l * 2 + 1) * 8192;
        const uint2* w2h = w2f + (l * 2 + 0) * 8192;
        const uint2* w2l = w2f + (l * 2 + 1) * 8192;
        edge_gemm_kernel<<<gemmBlocks, 256>>>(ea, bfh, bfl, Ebuf, nEdges);
        agg_kernel<<<aggBlocks, 256>>>(cur, Ebuf, be + (size_t)l * CH, agg, nNodes);
        mlp_mma_kernel<<<mlpBlocks, 256, MLP2_SMEM>>>(
            cur, agg, w1h, w1l, w2h, w2l,
            b1 + (size_t)l * 256, b2 + (size_t)l * CH,
            lnw + (size_t)l * CH, lnb + (size_t)l * CH, nxt, nNodes);
        cur = nxt;
    }
    proj_kernel<<<projBlocks, 256>>>(cur, Wout, bout, out, nNodes);
}